// round 1
// baseline (speedup 1.0000x reference)
#include <cuda_runtime.h>

#define Bb 64
#define Tt 64
#define Hh 1024
#define Vv 32000
#define Ee 512

// ---------------- scratch (static device memory; no allocation) ----------------
__device__ float g_xbuf[Tt * Bb * Ee];     // embedded inputs, [t][b][e]   (8 MB)
__device__ float g_h[8 * Bb * Hh];         // 4 layers x 2 ping-pong h     (2 MB)
__device__ float g_c[4 * Bb * Hh];         // 4 layers c                   (1 MB)
__device__ float g_h4[Tt * Bb * Hh];       // stacked h4 outputs, [t][b][h] (16 MB)

// ---------------- embedding lookup: xbuf[t][b][e] = emb[tok[b][t]][e] ----------
__global__ __launch_bounds__(256) void embed_k(const int* __restrict__ tok,
                                               const float* __restrict__ emb) {
    int idx = blockIdx.x * 256 + threadIdx.x;       // over T*B*E = 2,097,152
    int e  = idx & (Ee - 1);
    int bt = idx >> 9;                              // /E
    int b  = bt & (Bb - 1);
    int t  = bt >> 6;
    g_xbuf[idx] = emb[(size_t)tok[b * Tt + t] * Ee + e];
}

// ---------------- fused LSTM cell: z = x@W + h@U + b; gates; h,c update -------
// Block: 8 hidden units (j0..j0+7) x all 64 batch rows x 4 gates = C tile [64 x 32]
// 128 threads, thread tile = 8 rows x 2 cols. Grid = H/8 = 128 blocks.
__global__ __launch_bounds__(128) void lstm_cell_k(
    const float* __restrict__ x, int Kx,            // [64, Kx]
    const float* __restrict__ hprev,                // [64, H]
    const float* __restrict__ W,                    // [Kx, 4H]
    const float* __restrict__ U,                    // [H, 4H]
    const float* __restrict__ bias,                 // [4H]
    float* __restrict__ c,                          // [64, H] (in-place)
    float* __restrict__ hnew,                       // [64, H]
    float* __restrict__ h4store)                    // [64, H] or nullptr
{
    __shared__ float As[16][68];   // [k][row], padded, float4-aligned rows
    __shared__ float Bs[16][32];   // [k][col], col = gate*8 + jj
    __shared__ float Zs[64][33];   // z tile for gate epilogue

    const int tid = threadIdx.x;
    const int tx  = tid & 15;      // col pair index (cols 2*tx, 2*tx+1)
    const int ty  = tid >> 4;      // row group (rows ty*8 .. ty*8+7)
    const int j0  = blockIdx.x * 8;

    float acc[8][2];
#pragma unroll
    for (int i = 0; i < 8; i++) { acc[i][0] = 0.f; acc[i][1] = 0.f; }

#pragma unroll 1
    for (int phase = 0; phase < 2; ++phase) {
        const float* A  = phase ? hprev : x;
        const float* Bm = phase ? U : W;
        const int K     = phase ? Hh : Kx;
#pragma unroll 1
        for (int k0 = 0; k0 < K; k0 += 16) {
            // load A tile [64 rows x 16 k], transposed into As[k][row]
            {
                int r   = tid >> 1;
                int kk0 = (tid & 1) * 8;
                const float* ap = A + (size_t)r * K + k0 + kk0;
                float4 v0 = *(const float4*)(ap);
                float4 v1 = *(const float4*)(ap + 4);
                As[kk0 + 0][r] = v0.x; As[kk0 + 1][r] = v0.y;
                As[kk0 + 2][r] = v0.z; As[kk0 + 3][r] = v0.w;
                As[kk0 + 4][r] = v1.x; As[kk0 + 5][r] = v1.y;
                As[kk0 + 6][r] = v1.z; As[kk0 + 7][r] = v1.w;
            }
            // load B tile [16 k x 32 cols] (cols map to gate*H + j0 + jj)
#pragma unroll
            for (int i = 0; i < 4; i++) {
                int e  = tid + 128 * i;
                int kk = e >> 5, cc = e & 31;
                Bs[kk][cc] = Bm[(size_t)(k0 + kk) * (4 * Hh) + (cc >> 3) * Hh + j0 + (cc & 7)];
            }
            __syncthreads();
#pragma unroll
            for (int kk = 0; kk < 16; kk++) {
                float4 a0 = *(const float4*)&As[kk][ty * 8];
                float4 a1 = *(const float4*)&As[kk][ty * 8 + 4];
                float b0 = Bs[kk][2 * tx];
                float b1 = Bs[kk][2 * tx + 1];
                acc[0][0] = fmaf(a0.x, b0, acc[0][0]); acc[0][1] = fmaf(a0.x, b1, acc[0][1]);
                acc[1][0] = fmaf(a0.y, b0, acc[1][0]); acc[1][1] = fmaf(a0.y, b1, acc[1][1]);
                acc[2][0] = fmaf(a0.z, b0, acc[2][0]); acc[2][1] = fmaf(a0.z, b1, acc[2][1]);
                acc[3][0] = fmaf(a0.w, b0, acc[3][0]); acc[3][1] = fmaf(a0.w, b1, acc[3][1]);
                acc[4][0] = fmaf(a1.x, b0, acc[4][0]); acc[4][1] = fmaf(a1.x, b1, acc[4][1]);
                acc[5][0] = fmaf(a1.y, b0, acc[5][0]); acc[5][1] = fmaf(a1.y, b1, acc[5][1]);
                acc[6][0] = fmaf(a1.z, b0, acc[6][0]); acc[6][1] = fmaf(a1.z, b1, acc[6][1]);
                acc[7][0] = fmaf(a1.w, b0, acc[7][0]); acc[7][1] = fmaf(a1.w, b1, acc[7][1]);
            }
            __syncthreads();
        }
    }

    // stash z tile to smem for the gate epilogue
#pragma unroll
    for (int i = 0; i < 8; i++) {
        Zs[ty * 8 + i][2 * tx]     = acc[i][0];
        Zs[ty * 8 + i][2 * tx + 1] = acc[i][1];
    }
    __syncthreads();

    // gate epilogue: 64 rows x 8 units = 512 cells, 4 per thread
#pragma unroll
    for (int q = 0; q < 4; q++) {
        int e  = tid + 128 * q;       // 0..511
        int r  = e >> 3;
        int jj = e & 7;
        int j  = j0 + jj;
        float zi = Zs[r][0  + jj] + bias[j];
        float zf = Zs[r][8  + jj] + bias[Hh + j];
        float zg = Zs[r][16 + jj] + bias[2 * Hh + j];
        float zo = Zs[r][24 + jj] + bias[3 * Hh + j];
        float si = 1.f / (1.f + __expf(-zi));
        float sf = 1.f / (1.f + __expf(-zf));
        float so = 1.f / (1.f + __expf(-zo));
        float tg = tanhf(zg);
        float cn = sf * c[r * Hh + j] + si * tg;
        float hn = so * tanhf(cn);
        c[r * Hh + j]    = cn;
        hnew[r * Hh + j] = hn;
        if (h4store) h4store[r * Hh + j] = hn;
    }
}

// ---------------- final FC: logits[(t,b), V] = h4 @ Wfc + bfc ------------------
// Block tile 128x128, 256 threads, 8x8 per thread. Grid x = row tile (so all
// row tiles sharing a Wfc column tile run adjacently -> Wfc read ~once from HBM).
__global__ __launch_bounds__(256) void fc_k(
    const float* __restrict__ A,     // g_h4, [4096, 1024] rows = t*64 + b
    const float* __restrict__ Wfc,   // [1024, 32000]
    const float* __restrict__ bfc,   // [32000]
    float* __restrict__ out)         // [B, T, V]
{
    __shared__ float As[8][132];
    __shared__ float Bs[8][128];
    const int tid  = threadIdx.x;
    const int row0 = blockIdx.x * 128;     // 0..31
    const int col0 = blockIdx.y * 128;     // 0..249
    const int tx   = tid & 15;
    const int ty   = tid >> 4;

    float acc[8][8];
#pragma unroll
    for (int i = 0; i < 8; i++)
#pragma unroll
        for (int j = 0; j < 8; j++) acc[i][j] = 0.f;

#pragma unroll 1
    for (int k0 = 0; k0 < Hh; k0 += 8) {
        {
            int r = tid >> 1, kk0 = (tid & 1) * 4;
            float4 v = *(const float4*)(A + (size_t)(row0 + r) * Hh + k0 + kk0);
            As[kk0 + 0][r] = v.x; As[kk0 + 1][r] = v.y;
            As[kk0 + 2][r] = v.z; As[kk0 + 3][r] = v.w;
        }
        {
            int kk = tid >> 5, cc = (tid & 31) * 4;
            *(float4*)&Bs[kk][cc] =
                *(const float4*)(Wfc + (size_t)(k0 + kk) * Vv + col0 + cc);
        }
        __syncthreads();
#pragma unroll
        for (int kk = 0; kk < 8; kk++) {
            float a[8], b[8];
            *(float4*)(a)     = *(const float4*)&As[kk][ty * 8];
            *(float4*)(a + 4) = *(const float4*)&As[kk][ty * 8 + 4];
            *(float4*)(b)     = *(const float4*)&Bs[kk][tx * 8];
            *(float4*)(b + 4) = *(const float4*)&Bs[kk][tx * 8 + 4];
#pragma unroll
            for (int i = 0; i < 8; i++)
#pragma unroll
                for (int j = 0; j < 8; j++) acc[i][j] = fmaf(a[i], b[j], acc[i][j]);
        }
        __syncthreads();
    }

    float bv[8];
#pragma unroll
    for (int j = 0; j < 8; j++) bv[j] = bfc[col0 + tx * 8 + j];

#pragma unroll
    for (int i = 0; i < 8; i++) {
        int r = row0 + ty * 8 + i;
        int t = r >> 6, b = r & 63;                      // A row = t*64 + b
        float* o = out + ((size_t)b * Tt + t) * Vv + col0 + tx * 8;
        float4 v0, v1;
        v0.x = acc[i][0] + bv[0]; v0.y = acc[i][1] + bv[1];
        v0.z = acc[i][2] + bv[2]; v0.w = acc[i][3] + bv[3];
        v1.x = acc[i][4] + bv[4]; v1.y = acc[i][5] + bv[5];
        v1.z = acc[i][6] + bv[6]; v1.w = acc[i][7] + bv[7];
        *(float4*)(o)     = v0;
        *(float4*)(o + 4) = v1;
    }
}

// ---------------- in-place row softmax over V=32000 ----------------------------
__global__ __launch_bounds__(256) void softmax_k(float* __restrict__ out) {
    __shared__ float red[256];
    float* p = out + (size_t)blockIdx.x * Vv;
    int tid = threadIdx.x;

    float m = -3.4e38f;
    for (int i = tid; i < Vv; i += 256) m = fmaxf(m, p[i]);
    red[tid] = m; __syncthreads();
    for (int s = 128; s > 0; s >>= 1) {
        if (tid < s) red[tid] = fmaxf(red[tid], red[tid + s]);
        __syncthreads();
    }
    m = red[0]; __syncthreads();

    float s = 0.f;
    for (int i = tid; i < Vv; i += 256) s += __expf(p[i] - m);
    red[tid] = s; __syncthreads();
    for (int st = 128; st > 0; st >>= 1) {
        if (tid < st) red[tid] += red[tid + st];
        __syncthreads();
    }
    float inv = 1.f / red[0];

    for (int i = tid; i < Vv; i += 256) p[i] = __expf(p[i] - m) * inv;
}

// ---------------- launch ------------------------------------------------------
extern "C" void kernel_launch(void* const* d_in, const int* in_sizes, int n_in,
                              void* d_out, int out_size) {
    (void)in_sizes; (void)n_in; (void)out_size;
    // metadata order = reference signature order:
    // 0: batch_target_in, 1..8: h1,c1,h2,c2,h3,c3,h4,c4, 9: emb,
    // 10..21: W1,U1,b1, W2,U2,b2, W3,U3,b3, W4,U4,b4, 22: Wfc, 23: bfc
    const int*   tok = (const int*)d_in[0];
    const float* emb = (const float*)d_in[9];
    const float* W[4]  = {(const float*)d_in[10], (const float*)d_in[13],
                          (const float*)d_in[16], (const float*)d_in[19]};
    const float* U[4]  = {(const float*)d_in[11], (const float*)d_in[14],
                          (const float*)d_in[17], (const float*)d_in[20]};
    const float* bi[4] = {(const float*)d_in[12], (const float*)d_in[15],
                          (const float*)d_in[18], (const float*)d_in[21]};
    const float* Wfc = (const float*)d_in[22];
    const float* bfc = (const float*)d_in[23];
    float* out = (float*)d_out;

    float *xbuf, *hbuf, *cbuf, *h4;
    cudaGetSymbolAddress((void**)&xbuf, g_xbuf);
    cudaGetSymbolAddress((void**)&hbuf, g_h);
    cudaGetSymbolAddress((void**)&cbuf, g_c);
    cudaGetSymbolAddress((void**)&h4,   g_h4);

    const size_t SH = (size_t)Bb * Hh;   // 65536 elems per state matrix

    // initialize recurrent state (ping slot 0) from inputs
    for (int l = 0; l < 4; l++) {
        cudaMemcpyAsync(hbuf + (size_t)(l * 2 + 0) * SH, d_in[1 + 2 * l],
                        SH * sizeof(float), cudaMemcpyDeviceToDevice, 0);
        cudaMemcpyAsync(cbuf + (size_t)l * SH, d_in[2 + 2 * l],
                        SH * sizeof(float), cudaMemcpyDeviceToDevice, 0);
    }

    embed_k<<<(Tt * Bb * Ee) / 256, 256>>>(tok, emb);

    for (int t = 0; t < Tt; t++) {
        int p = t & 1;
        for (int l = 0; l < 4; l++) {
            const float* xin = (l == 0)
                ? (xbuf + (size_t)t * Bb * Ee)
                : (hbuf + (size_t)((l - 1) * 2 + (p ^ 1)) * SH);
            int Kx = (l == 0) ? Ee : Hh;
            lstm_cell_k<<<Hh / 8, 128>>>(
                xin, Kx,
                hbuf + (size_t)(l * 2 + p) * SH,
                W[l], U[l], bi[l],
                cbuf + (size_t)l * SH,
                hbuf + (size_t)(l * 2 + (p ^ 1)) * SH,
                (l == 3) ? (h4 + (size_t)t * SH) : nullptr);
        }
    }

    fc_k<<<dim3(4096 / 128, Vv / 128), 256>>>(h4, Wfc, bfc, out);
    softmax_k<<<Bb * Tt, 256>>>(out);
}

// round 2
// speedup vs baseline: 2.0474x; 2.0474x over previous
#include <cuda_runtime.h>

#define Bb 64
#define Tt 64
#define Hh 1024
#define Vv 32000
#define Ee 512

// ---------------- scratch (static device memory; no allocation) ----------------
__device__ float g_xbuf[Tt * Bb * Ee];         // embedded inputs, [t][b][e]   (8 MB)
__device__ float g_h[8 * Bb * Hh];             // 4 layers x 2 ping-pong h     (2 MB)
__device__ float g_c[4 * Bb * Hh];             // 4 layers c                   (1 MB)
__device__ float g_h4[Tt * Bb * Hh];           // stacked h4 outputs           (16 MB)
__device__ float g_zpre[Tt * Bb * 4 * Hh];     // precomputed x@W1 per step    (64 MB)

// ---------------- cp.async helper ----------------------------------------------
__device__ __forceinline__ void cp16(void* smem_dst, const void* gsrc) {
    unsigned s = (unsigned)__cvta_generic_to_shared(smem_dst);
    asm volatile("cp.async.cg.shared.global [%0], [%1], 16;\n" :: "r"(s), "l"(gsrc));
}
__device__ __forceinline__ void cp_commit() {
    asm volatile("cp.async.commit_group;\n" ::: "memory");
}
__device__ __forceinline__ void cp_wait1() {
    asm volatile("cp.async.wait_group 1;\n" ::: "memory");
}
__device__ __forceinline__ void cp_wait0() {
    asm volatile("cp.async.wait_group 0;\n" ::: "memory");
}

// ---------------- embedding lookup: xbuf[t][b][e] = emb[tok[b][t]][e] ----------
__global__ __launch_bounds__(256) void embed_k(const int* __restrict__ tok,
                                               const float* __restrict__ emb) {
    int idx = blockIdx.x * 256 + threadIdx.x;       // over T*B*E
    int e  = idx & (Ee - 1);
    int bt = idx >> 9;
    int b  = bt & (Bb - 1);
    int t  = bt >> 6;
    g_xbuf[idx] = emb[(size_t)tok[b * Tt + t] * Ee + e];
}

// ---------------- fused LSTM cell with cp.async double buffering ---------------
// z = (optional x@W over n1*16 K) + h@U (K=1024) [+ zpre] + bias; gates; h,c.
// Block: C tile [64 rows x 32 cols] where cols = 4 gates x 8 units (j0..j0+7).
// 128 threads, thread tile 8 rows x 2 cols. Grid = H/8 = 128 blocks.
__global__ __launch_bounds__(128) void lstm_cell_k(
    const float* __restrict__ x,      // [64, 1024] (layer input) or unused
    const float* __restrict__ W,      // [1024, 4H] or unused
    int n1,                           // # of 16-wide K chunks for x@W (0 or 64)
    const float* __restrict__ hprev,  // [64, 1024]
    const float* __restrict__ U,      // [1024, 4H]
    const float* __restrict__ bias,   // [4H]
    const float* __restrict__ zpre,   // [64, 4H] precomputed x@W1, or nullptr
    float* __restrict__ c,            // [64, H] (in-place)
    float* __restrict__ hnew,         // [64, H]
    float* __restrict__ h4store)      // [64, H] or nullptr
{
    __shared__ float As[2][64][20];   // A tile [row][k], row-major (20 = 16 + pad)
    __shared__ float Bs[2][16][32];   // B tile [k][col]
    __shared__ float Zs[64][33];      // z tile for gate epilogue

    const int tid = threadIdx.x;
    const int tx  = tid & 15;         // col pair (2*tx, 2*tx+1)
    const int ty  = tid >> 4;         // row group (8 rows)
    const int j0  = blockIdx.x * 8;
    const int n   = n1 + 64;          // total 16-wide K chunks

    // per-thread cp.async coordinates
    const int ac0 = tid * 2;                     // A chunks: 256 total (16B each)
    const int ar0 = ac0 >> 2,       ao0 = (ac0 & 3) << 2;
    const int ar1 = (ac0 + 1) >> 2, ao1 = ((ac0 + 1) & 3) << 2;
    const int bkk = tid >> 3,       bc4 = (tid & 7) * 4;   // B chunk: 128 total
    const int bgo = (bc4 >> 3) * Hh + j0 + (bc4 & 7);

    float acc[8][2];
#pragma unroll
    for (int i = 0; i < 8; i++) { acc[i][0] = 0.f; acc[i][1] = 0.f; }

    auto issue = [&](int i, int buf) {
        const float* Ai; const float* Bi; int k0;
        if (i < n1) { Ai = x;     Bi = W; k0 = i * 16; }
        else        { Ai = hprev; Bi = U; k0 = (i - n1) * 16; }
        cp16(&As[buf][ar0][ao0], Ai + (size_t)ar0 * Hh + k0 + ao0);
        cp16(&As[buf][ar1][ao1], Ai + (size_t)ar1 * Hh + k0 + ao1);
        cp16(&Bs[buf][bkk][bc4], Bi + (size_t)(k0 + bkk) * (4 * Hh) + bgo);
        cp_commit();
    };

    issue(0, 0);

#pragma unroll 1
    for (int i = 0; i < n; i++) {
        if (i + 1 < n) { issue(i + 1, (i + 1) & 1); cp_wait1(); }
        else           { cp_wait0(); }
        __syncthreads();
        const int buf = i & 1;
#pragma unroll
        for (int kk = 0; kk < 16; kk++) {
            float2 b2 = *(const float2*)&Bs[buf][kk][2 * tx];
            float a[8];
#pragma unroll
            for (int r = 0; r < 8; r++) a[r] = As[buf][ty * 8 + r][kk];
#pragma unroll
            for (int r = 0; r < 8; r++) {
                acc[r][0] = fmaf(a[r], b2.x, acc[r][0]);
                acc[r][1] = fmaf(a[r], b2.y, acc[r][1]);
            }
        }
        __syncthreads();
    }

    // stash z tile to smem for the gate epilogue
#pragma unroll
    for (int i = 0; i < 8; i++) {
        Zs[ty * 8 + i][2 * tx]     = acc[i][0];
        Zs[ty * 8 + i][2 * tx + 1] = acc[i][1];
    }
    __syncthreads();

    // gate epilogue: 64 rows x 8 units = 512 cells, 4 per thread
#pragma unroll
    for (int q = 0; q < 4; q++) {
        int e  = tid + 128 * q;
        int r  = e >> 3;
        int jj = e & 7;
        int j  = j0 + jj;
        float zi = Zs[r][0  + jj] + bias[j];
        float zf = Zs[r][8  + jj] + bias[Hh + j];
        float zg = Zs[r][16 + jj] + bias[2 * Hh + j];
        float zo = Zs[r][24 + jj] + bias[3 * Hh + j];
        if (zpre) {
            const float* zp = zpre + (size_t)r * (4 * Hh);
            zi += zp[j];
            zf += zp[Hh + j];
            zg += zp[2 * Hh + j];
            zo += zp[3 * Hh + j];
        }
        float si = 1.f / (1.f + __expf(-zi));
        float sf = 1.f / (1.f + __expf(-zf));
        float so = 1.f / (1.f + __expf(-zo));
        float tg = tanhf(zg);
        float cn = sf * c[r * Hh + j] + si * tg;
        float hn = so * tanhf(cn);
        c[r * Hh + j]    = cn;
        hnew[r * Hh + j] = hn;
        if (h4store) h4store[r * Hh + j] = hn;
    }
}

// ---------------- generic 128x128-tile GEMM: C = A@B (+bias) (opt. permute) ----
// A [4096, K] row-major, B [K, N] row-major. 256 threads, 8x8 per thread.
// perm=1: A row r=(t*64+b) stored to out row (b*T + t) (for the FC output).
__global__ __launch_bounds__(256) void gemm128_k(
    const float* __restrict__ A,
    const float* __restrict__ Bm,
    const float* __restrict__ bias,   // or nullptr
    float* __restrict__ out,
    int K, int N, int perm)
{
    __shared__ float As[8][132];
    __shared__ float Bs[8][128];
    const int tid  = threadIdx.x;
    const int row0 = blockIdx.x * 128;
    const int col0 = blockIdx.y * 128;
    const int tx   = tid & 15;
    const int ty   = tid >> 4;

    float acc[8][8];
#pragma unroll
    for (int i = 0; i < 8; i++)
#pragma unroll
        for (int j = 0; j < 8; j++) acc[i][j] = 0.f;

#pragma unroll 1
    for (int k0 = 0; k0 < K; k0 += 8) {
        {
            int r = tid >> 1, kk0 = (tid & 1) * 4;
            float4 v = *(const float4*)(A + (size_t)(row0 + r) * K + k0 + kk0);
            As[kk0 + 0][r] = v.x; As[kk0 + 1][r] = v.y;
            As[kk0 + 2][r] = v.z; As[kk0 + 3][r] = v.w;
        }
        {
            int kk = tid >> 5, cc = (tid & 31) * 4;
            *(float4*)&Bs[kk][cc] =
                *(const float4*)(Bm + (size_t)(k0 + kk) * N + col0 + cc);
        }
        __syncthreads();
#pragma unroll
        for (int kk = 0; kk < 8; kk++) {
            float a[8], b[8];
            *(float4*)(a)     = *(const float4*)&As[kk][ty * 8];
            *(float4*)(a + 4) = *(const float4*)&As[kk][ty * 8 + 4];
            *(float4*)(b)     = *(const float4*)&Bs[kk][tx * 8];
            *(float4*)(b + 4) = *(const float4*)&Bs[kk][tx * 8 + 4];
#pragma unroll
            for (int i = 0; i < 8; i++)
#pragma unroll
                for (int j = 0; j < 8; j++) acc[i][j] = fmaf(a[i], b[j], acc[i][j]);
        }
        __syncthreads();
    }

    float bv[8];
#pragma unroll
    for (int j = 0; j < 8; j++) bv[j] = bias ? bias[col0 + tx * 8 + j] : 0.f;

#pragma unroll
    for (int i = 0; i < 8; i++) {
        int r = row0 + ty * 8 + i;
        float* o;
        if (perm) {
            int t = r >> 6, b = r & 63;
            o = out + ((size_t)b * Tt + t) * N + col0 + tx * 8;
        } else {
            o = out + (size_t)r * N + col0 + tx * 8;
        }
        float4 v0, v1;
        v0.x = acc[i][0] + bv[0]; v0.y = acc[i][1] + bv[1];
        v0.z = acc[i][2] + bv[2]; v0.w = acc[i][3] + bv[3];
        v1.x = acc[i][4] + bv[4]; v1.y = acc[i][5] + bv[5];
        v1.z = acc[i][6] + bv[6]; v1.w = acc[i][7] + bv[7];
        *(float4*)(o)     = v0;
        *(float4*)(o + 4) = v1;
    }
}

// ---------------- in-place row softmax over V=32000 ----------------------------
__global__ __launch_bounds__(256) void softmax_k(float* __restrict__ out) {
    __shared__ float red[256];
    float* p = out + (size_t)blockIdx.x * Vv;
    int tid = threadIdx.x;

    float m = -3.4e38f;
    for (int i = tid; i < Vv; i += 256) m = fmaxf(m, p[i]);
    red[tid] = m; __syncthreads();
    for (int s = 128; s > 0; s >>= 1) {
        if (tid < s) red[tid] = fmaxf(red[tid], red[tid + s]);
        __syncthreads();
    }
    m = red[0]; __syncthreads();

    float s = 0.f;
    for (int i = tid; i < Vv; i += 256) s += __expf(p[i] - m);
    red[tid] = s; __syncthreads();
    for (int st = 128; st > 0; st >>= 1) {
        if (tid < st) red[tid] += red[tid + st];
        __syncthreads();
    }
    float inv = 1.f / red[0];

    for (int i = tid; i < Vv; i += 256) p[i] = __expf(p[i] - m) * inv;
}

// ---------------- launch ------------------------------------------------------
extern "C" void kernel_launch(void* const* d_in, const int* in_sizes, int n_in,
                              void* d_out, int out_size) {
    (void)in_sizes; (void)n_in; (void)out_size;
    // 0: batch_target_in, 1..8: h1,c1..h4,c4, 9: emb,
    // 10..21: W1,U1,b1 .. W4,U4,b4, 22: Wfc, 23: bfc
    const int*   tok = (const int*)d_in[0];
    const float* emb = (const float*)d_in[9];
    const float* W[4]  = {(const float*)d_in[10], (const float*)d_in[13],
                          (const float*)d_in[16], (const float*)d_in[19]};
    const float* U[4]  = {(const float*)d_in[11], (const float*)d_in[14],
                          (const float*)d_in[17], (const float*)d_in[20]};
    const float* bi[4] = {(const float*)d_in[12], (const float*)d_in[15],
                          (const float*)d_in[18], (const float*)d_in[21]};
    const float* Wfc = (const float*)d_in[22];
    const float* bfc = (const float*)d_in[23];
    float* out = (float*)d_out;

    float *xbuf, *hbuf, *cbuf, *h4, *zpre;
    cudaGetSymbolAddress((void**)&xbuf, g_xbuf);
    cudaGetSymbolAddress((void**)&hbuf, g_h);
    cudaGetSymbolAddress((void**)&cbuf, g_c);
    cudaGetSymbolAddress((void**)&h4,   g_h4);
    cudaGetSymbolAddress((void**)&zpre, g_zpre);

    const size_t SH = (size_t)Bb * Hh;

    for (int l = 0; l < 4; l++) {
        cudaMemcpyAsync(hbuf + (size_t)(l * 2 + 0) * SH, d_in[1 + 2 * l],
                        SH * sizeof(float), cudaMemcpyDeviceToDevice, 0);
        cudaMemcpyAsync(cbuf + (size_t)l * SH, d_in[2 + 2 * l],
                        SH * sizeof(float), cudaMemcpyDeviceToDevice, 0);
    }

    embed_k<<<(Tt * Bb * Ee) / 256, 256>>>(tok, emb);

    // hoisted layer-1 input contribution: zpre[t*64+b][:] = x[t,b,:] @ W1
    gemm128_k<<<dim3(4096 / 128, (4 * Hh) / 128), 256>>>(
        xbuf, W[0], nullptr, zpre, Ee, 4 * Hh, 0);

    for (int t = 0; t < Tt; t++) {
        int p = t & 1;
        for (int l = 0; l < 4; l++) {
            const float* xin = (l == 0)
                ? nullptr
                : (hbuf + (size_t)((l - 1) * 2 + (p ^ 1)) * SH);
            lstm_cell_k<<<Hh / 8, 128>>>(
                (l == 0) ? hbuf : xin,              // dummy for l==0
                (l == 0) ? U[0] : W[l],             // dummy for l==0
                (l == 0) ? 0 : 64,
                hbuf + (size_t)(l * 2 + p) * SH,
                U[l], bi[l],
                (l == 0) ? (zpre + (size_t)t * Bb * 4 * Hh) : nullptr,
                cbuf + (size_t)l * SH,
                hbuf + (size_t)(l * 2 + (p ^ 1)) * SH,
                (l == 3) ? (h4 + (size_t)t * SH) : nullptr);
        }
    }

    gemm128_k<<<dim3(4096 / 128, Vv / 128), 256>>>(h4, Wfc, bfc, out, Hh, Vv, 1);
    softmax_k<<<Bb * Tt, 256>>>(out);
}

// round 3
// speedup vs baseline: 2.9233x; 1.4278x over previous
#include <cuda_runtime.h>

#define Bb 64
#define Tt 64
#define Hh 1024
#define Vv 32000
#define Ee 512

// ---------------- scratch (static device memory; no allocation) ----------------
__device__ float g_xbuf[Tt * Bb * Ee];         // embedded inputs, [t][b][e]
__device__ float g_h[8 * Bb * Hh];             // 4 layers x 2 ping-pong h
__device__ float g_c[4 * Bb * Hh];             // 4 layers c
__device__ float g_h4[Tt * Bb * Hh];           // stacked h4 outputs
__device__ float g_zpre[Tt * Bb * 4 * Hh];     // precomputed x@W1 per step

struct CellArgs {
    const float* W[4];
    const float* U[4];
    const float* b[4];
};

// ---------------- cp.async helpers ---------------------------------------------
__device__ __forceinline__ void cp16(void* smem_dst, const void* gsrc) {
    unsigned s = (unsigned)__cvta_generic_to_shared(smem_dst);
    asm volatile("cp.async.cg.shared.global [%0], [%1], 16;\n" :: "r"(s), "l"(gsrc));
}
__device__ __forceinline__ void cp_commit() {
    asm volatile("cp.async.commit_group;\n" ::: "memory");
}
__device__ __forceinline__ void cp_wait1() {
    asm volatile("cp.async.wait_group 1;\n" ::: "memory");
}
__device__ __forceinline__ void cp_wait0() {
    asm volatile("cp.async.wait_group 0;\n" ::: "memory");
}

// ---------------- embedding lookup ---------------------------------------------
__global__ __launch_bounds__(256) void embed_k(const int* __restrict__ tok,
                                               const float* __restrict__ emb) {
    int idx = blockIdx.x * 256 + threadIdx.x;
    int e  = idx & (Ee - 1);
    int bt = idx >> 9;
    int b  = bt & (Bb - 1);
    int t  = bt >> 6;
    g_xbuf[idx] = emb[(size_t)tok[b * Tt + t] * Ee + e];
}

// ---------------- wavefront LSTM cell ------------------------------------------
// One launch per diagonal s = t + l. blockIdx.y selects the active (t, l) cell;
// blockIdx.x selects 8 hidden units. Per cell: z = x@W + h@U (+zpre) + bias,
// then gate math. Block tile: C [64 rows x 32 cols(4 gates x 8 units)],
// 128 threads, 8x2 per thread, cp.async double buffered.
__global__ __launch_bounds__(128) void lstm_wave_k(CellArgs args, int s) {
    __shared__ float As[2][64][20];
    __shared__ float Bs[2][16][32];
    __shared__ float Zs[64][33];

    const int lmin = (s > 63) ? (s - 63) : 0;
    const int l    = lmin + blockIdx.y;
    const int t    = s - l;
    const size_t SH = (size_t)Bb * Hh;

    const float* hprev = g_h + (size_t)(l * 2 + (t & 1)) * SH;
    float*       hnew  = g_h + (size_t)(l * 2 + ((t + 1) & 1)) * SH;
    float*       c     = g_c + (size_t)l * SH;
    const float* x     = (l == 0) ? hprev
                                  : g_h + (size_t)((l - 1) * 2 + ((t + 1) & 1)) * SH;
    const float* zpre  = (l == 0) ? (g_zpre + (size_t)t * Bb * 4 * Hh) : nullptr;
    float*       h4st  = (l == 3) ? (g_h4 + (size_t)t * SH) : nullptr;
    const float* W     = args.W[l];
    const float* U     = args.U[l];
    const float* bias  = args.b[l];
    const int    n1    = (l == 0) ? 0 : 64;    // x@W chunks (16-wide K)
    const int    n     = n1 + 64;

    const int tid = threadIdx.x;
    const int tx  = tid & 15;
    const int ty  = tid >> 4;
    const int j0  = blockIdx.x * 8;

    const int ac0 = tid * 2;
    const int ar0 = ac0 >> 2,       ao0 = (ac0 & 3) << 2;
    const int ar1 = (ac0 + 1) >> 2, ao1 = ((ac0 + 1) & 3) << 2;
    const int bkk = tid >> 3,       bc4 = (tid & 7) * 4;
    const int bgo = (bc4 >> 3) * Hh + j0 + (bc4 & 7);

    float acc[8][2];
#pragma unroll
    for (int i = 0; i < 8; i++) { acc[i][0] = 0.f; acc[i][1] = 0.f; }

    auto issue = [&](int i, int buf) {
        const float* Ai; const float* Bi; int k0;
        if (i < n1) { Ai = x;     Bi = W; k0 = i * 16; }
        else        { Ai = hprev; Bi = U; k0 = (i - n1) * 16; }
        cp16(&As[buf][ar0][ao0], Ai + (size_t)ar0 * Hh + k0 + ao0);
        cp16(&As[buf][ar1][ao1], Ai + (size_t)ar1 * Hh + k0 + ao1);
        cp16(&Bs[buf][bkk][bc4], Bi + (size_t)(k0 + bkk) * (4 * Hh) + bgo);
        cp_commit();
    };

    issue(0, 0);

#pragma unroll 1
    for (int i = 0; i < n; i++) {
        if (i + 1 < n) { issue(i + 1, (i + 1) & 1); cp_wait1(); }
        else           { cp_wait0(); }
        __syncthreads();
        const int buf = i & 1;
#pragma unroll
        for (int kk = 0; kk < 16; kk++) {
            float2 b2 = *(const float2*)&Bs[buf][kk][2 * tx];
            float a[8];
#pragma unroll
            for (int r = 0; r < 8; r++) a[r] = As[buf][ty * 8 + r][kk];
#pragma unroll
            for (int r = 0; r < 8; r++) {
                acc[r][0] = fmaf(a[r], b2.x, acc[r][0]);
                acc[r][1] = fmaf(a[r], b2.y, acc[r][1]);
            }
        }
        __syncthreads();
    }

#pragma unroll
    for (int i = 0; i < 8; i++) {
        Zs[ty * 8 + i][2 * tx]     = acc[i][0];
        Zs[ty * 8 + i][2 * tx + 1] = acc[i][1];
    }
    __syncthreads();

#pragma unroll
    for (int q = 0; q < 4; q++) {
        int e  = tid + 128 * q;
        int r  = e >> 3;
        int jj = e & 7;
        int j  = j0 + jj;
        float zi = Zs[r][0  + jj] + bias[j];
        float zf = Zs[r][8  + jj] + bias[Hh + j];
        float zg = Zs[r][16 + jj] + bias[2 * Hh + j];
        float zo = Zs[r][24 + jj] + bias[3 * Hh + j];
        if (zpre) {
            const float* zp = zpre + (size_t)r * (4 * Hh);
            zi += zp[j];
            zf += zp[Hh + j];
            zg += zp[2 * Hh + j];
            zo += zp[3 * Hh + j];
        }
        float si = 1.f / (1.f + __expf(-zi));
        float sf = 1.f / (1.f + __expf(-zf));
        float so = 1.f / (1.f + __expf(-zo));
        float tg = tanhf(zg);
        float cn = sf * c[r * Hh + j] + si * tg;
        float hn = so * tanhf(cn);
        c[r * Hh + j]    = cn;
        hnew[r * Hh + j] = hn;
        if (h4st) h4st[r * Hh + j] = hn;
    }
}

// ---------------- generic 128x128-tile GEMM ------------------------------------
__global__ __launch_bounds__(256) void gemm128_k(
    const float* __restrict__ A,
    const float* __restrict__ Bm,
    const float* __restrict__ bias,
    float* __restrict__ out,
    int K, int N, int perm)
{
    __shared__ float As[8][132];
    __shared__ float Bs[8][128];
    const int tid  = threadIdx.x;
    const int row0 = blockIdx.x * 128;
    const int col0 = blockIdx.y * 128;
    const int tx   = tid & 15;
    const int ty   = tid >> 4;

    float acc[8][8];
#pragma unroll
    for (int i = 0; i < 8; i++)
#pragma unroll
        for (int j = 0; j < 8; j++) acc[i][j] = 0.f;

#pragma unroll 1
    for (int k0 = 0; k0 < K; k0 += 8) {
        {
            int r = tid >> 1, kk0 = (tid & 1) * 4;
            float4 v = *(const float4*)(A + (size_t)(row0 + r) * K + k0 + kk0);
            As[kk0 + 0][r] = v.x; As[kk0 + 1][r] = v.y;
            As[kk0 + 2][r] = v.z; As[kk0 + 3][r] = v.w;
        }
        {
            int kk = tid >> 5, cc = (tid & 31) * 4;
            *(float4*)&Bs[kk][cc] =
                *(const float4*)(Bm + (size_t)(k0 + kk) * N + col0 + cc);
        }
        __syncthreads();
#pragma unroll
        for (int kk = 0; kk < 8; kk++) {
            float a[8], b[8];
            *(float4*)(a)     = *(const float4*)&As[kk][ty * 8];
            *(float4*)(a + 4) = *(const float4*)&As[kk][ty * 8 + 4];
            *(float4*)(b)     = *(const float4*)&Bs[kk][tx * 8];
            *(float4*)(b + 4) = *(const float4*)&Bs[kk][tx * 8 + 4];
#pragma unroll
            for (int i = 0; i < 8; i++)
#pragma unroll
                for (int j = 0; j < 8; j++) acc[i][j] = fmaf(a[i], b[j], acc[i][j]);
        }
        __syncthreads();
    }

    float bv[8];
#pragma unroll
    for (int j = 0; j < 8; j++) bv[j] = bias ? bias[col0 + tx * 8 + j] : 0.f;

#pragma unroll
    for (int i = 0; i < 8; i++) {
        int r = row0 + ty * 8 + i;
        float* o;
        if (perm) {
            int t = r >> 6, b = r & 63;
            o = out + ((size_t)b * Tt + t) * N + col0 + tx * 8;
        } else {
            o = out + (size_t)r * N + col0 + tx * 8;
        }
        float4 v0, v1;
        v0.x = acc[i][0] + bv[0]; v0.y = acc[i][1] + bv[1];
        v0.z = acc[i][2] + bv[2]; v0.w = acc[i][3] + bv[3];
        v1.x = acc[i][4] + bv[4]; v1.y = acc[i][5] + bv[5];
        v1.z = acc[i][6] + bv[6]; v1.w = acc[i][7] + bv[7];
        *(float4*)(o)     = v0;
        *(float4*)(o + 4) = v1;
    }
}

// ---------------- in-place row softmax over V ----------------------------------
__global__ __launch_bounds__(256) void softmax_k(float* __restrict__ out) {
    __shared__ float red[256];
    float* p = out + (size_t)blockIdx.x * Vv;
    int tid = threadIdx.x;

    float m = -3.4e38f;
    for (int i = tid; i < Vv; i += 256) m = fmaxf(m, p[i]);
    red[tid] = m; __syncthreads();
    for (int s = 128; s > 0; s >>= 1) {
        if (tid < s) red[tid] = fmaxf(red[tid], red[tid + s]);
        __syncthreads();
    }
    m = red[0]; __syncthreads();

    float s = 0.f;
    for (int i = tid; i < Vv; i += 256) s += __expf(p[i] - m);
    red[tid] = s; __syncthreads();
    for (int st = 128; st > 0; st >>= 1) {
        if (tid < st) red[tid] += red[tid + st];
        __syncthreads();
    }
    float inv = 1.f / red[0];

    for (int i = tid; i < Vv; i += 256) p[i] = __expf(p[i] - m) * inv;
}

// ---------------- launch ------------------------------------------------------
extern "C" void kernel_launch(void* const* d_in, const int* in_sizes, int n_in,
                              void* d_out, int out_size) {
    (void)in_sizes; (void)n_in; (void)out_size;
    const int*   tok = (const int*)d_in[0];
    const float* emb = (const float*)d_in[9];
    CellArgs args;
    for (int l = 0; l < 4; l++) {
        args.W[l] = (const float*)d_in[10 + 3 * l];
        args.U[l] = (const float*)d_in[11 + 3 * l];
        args.b[l] = (const float*)d_in[12 + 3 * l];
    }
    const float* Wfc = (const float*)d_in[22];
    const float* bfc = (const float*)d_in[23];
    float* out = (float*)d_out;

    float *xbuf, *hbuf, *cbuf, *h4, *zpre;
    cudaGetSymbolAddress((void**)&xbuf, g_xbuf);
    cudaGetSymbolAddress((void**)&hbuf, g_h);
    cudaGetSymbolAddress((void**)&cbuf, g_c);
    cudaGetSymbolAddress((void**)&h4,   g_h4);
    cudaGetSymbolAddress((void**)&zpre, g_zpre);

    const size_t SH = (size_t)Bb * Hh;

    for (int l = 0; l < 4; l++) {
        cudaMemcpyAsync(hbuf + (size_t)(l * 2 + 0) * SH, d_in[1 + 2 * l],
                        SH * sizeof(float), cudaMemcpyDeviceToDevice, 0);
        cudaMemcpyAsync(cbuf + (size_t)l * SH, d_in[2 + 2 * l],
                        SH * sizeof(float), cudaMemcpyDeviceToDevice, 0);
    }

    embed_k<<<(Tt * Bb * Ee) / 256, 256>>>(tok, emb);

    // hoisted layer-1 input contribution: zpre = x @ W1
    gemm128_k<<<dim3(4096 / 128, (4 * Hh) / 128), 256>>>(
        xbuf, args.W[0], nullptr, zpre, Ee, 4 * Hh, 0);

    // wavefront over diagonals s = t + l
    for (int s = 0; s <= Tt + 3 - 1; s++) {
        int lmin = (s > Tt - 1) ? (s - (Tt - 1)) : 0;
        int lmax = (s < 3) ? s : 3;
        int ny   = lmax - lmin + 1;
        lstm_wave_k<<<dim3(Hh / 8, ny), 128>>>(args, s);
    }

    gemm128_k<<<dim3(4096 / 128, Vv / 128), 256>>>(h4, Wfc, bfc, out, Hh, Vv, 1);
    softmax_k<<<Bb * Tt, 256>>>(out);
}

// round 4
// speedup vs baseline: 3.6524x; 1.2494x over previous
#include <cuda_runtime.h>
#include <cuda_bf16.h>

#define Bb 64
#define Tt 64
#define Hh 1024
#define Vv 32000
#define Ee 512

// ---------------- scratch (static device memory; no allocation) ----------------
__device__ float g_xbuf[Tt * Bb * Ee];          // embedded inputs
__device__ float g_h[8 * Bb * Hh];              // 4 layers x 2 ping-pong h
__device__ float g_c[4 * Bb * Hh];              // 4 layers c
__device__ float g_h4[Tt * Bb * Hh];            // stacked h4 outputs
__device__ float g_zpre[Tt * Bb * 4 * Hh];      // precomputed x@W1
__device__ __nv_bfloat16 g_Ahi[4096 * 1024];    // activation split (reused)
__device__ __nv_bfloat16 g_Alo[4096 * 1024];
__device__ __nv_bfloat16 g_B1hi[4096 * 512];    // W1^T split  [4H][E]
__device__ __nv_bfloat16 g_B1lo[4096 * 512];
__device__ __nv_bfloat16 g_Bhi[(size_t)Vv * 1024];  // Wfc^T split [V][H]
__device__ __nv_bfloat16 g_Blo[(size_t)Vv * 1024];

struct CellArgs {
    const float* W[4];
    const float* U[4];
    const float* b[4];
};

// ---------------- cp.async helpers ---------------------------------------------
__device__ __forceinline__ void cp16(void* smem_dst, const void* gsrc) {
    unsigned s = (unsigned)__cvta_generic_to_shared(smem_dst);
    asm volatile("cp.async.cg.shared.global [%0], [%1], 16;\n" :: "r"(s), "l"(gsrc));
}
__device__ __forceinline__ void cp_commit() {
    asm volatile("cp.async.commit_group;\n" ::: "memory");
}
__device__ __forceinline__ void cp_wait1() {
    asm volatile("cp.async.wait_group 1;\n" ::: "memory");
}
__device__ __forceinline__ void cp_wait0() {
    asm volatile("cp.async.wait_group 0;\n" ::: "memory");
}

// ---------------- bf16 mma helper ----------------------------------------------
__device__ __forceinline__ void mma16816(float c[4],
                                         unsigned a0, unsigned a1, unsigned a2, unsigned a3,
                                         unsigned b0, unsigned b1) {
    asm volatile(
        "mma.sync.aligned.m16n8k16.row.col.f32.bf16.bf16.f32 "
        "{%0,%1,%2,%3}, {%4,%5,%6,%7}, {%8,%9}, {%0,%1,%2,%3};"
        : "+f"(c[0]), "+f"(c[1]), "+f"(c[2]), "+f"(c[3])
        : "r"(a0), "r"(a1), "r"(a2), "r"(a3), "r"(b0), "r"(b1));
}

// ---------------- embedding lookup ---------------------------------------------
__global__ __launch_bounds__(256) void embed_k(const int* __restrict__ tok,
                                               const float* __restrict__ emb) {
    int idx = blockIdx.x * 256 + threadIdx.x;
    int e  = idx & (Ee - 1);
    int bt = idx >> 9;
    int b  = bt & (Bb - 1);
    int t  = bt >> 6;
    g_xbuf[idx] = emb[(size_t)tok[b * Tt + t] * Ee + e];
}

// ---------------- fp32 -> (hi, lo) bf16 split ----------------------------------
__global__ __launch_bounds__(256) void split_k(const float* __restrict__ src,
                                               __nv_bfloat16* __restrict__ hi,
                                               __nv_bfloat16* __restrict__ lo, int n) {
    int i = blockIdx.x * 256 + threadIdx.x;
    if (i < n) {
        float x = src[i];
        __nv_bfloat16 h = __float2bfloat16(x);
        hi[i] = h;
        lo[i] = __float2bfloat16(x - __bfloat162float(h));
    }
}

// ---------------- transpose + split: src[K][N] -> hi/lo [N][K] ------------------
__global__ __launch_bounds__(256) void tsplit_k(const float* __restrict__ src,
                                                __nv_bfloat16* __restrict__ hi,
                                                __nv_bfloat16* __restrict__ lo,
                                                int K, int N) {
    __shared__ float tile[32][33];
    int k0 = blockIdx.x * 32, n0 = blockIdx.y * 32;
    int tx = threadIdx.x & 31, ty = threadIdx.x >> 5;    // 32 x 8
#pragma unroll
    for (int j = 0; j < 32; j += 8)
        tile[ty + j][tx] = src[(size_t)(k0 + ty + j) * N + n0 + tx];
    __syncthreads();
#pragma unroll
    for (int j = 0; j < 32; j += 8) {
        float x = tile[tx][ty + j];
        __nv_bfloat16 h = __float2bfloat16(x);
        size_t o = (size_t)(n0 + ty + j) * K + k0 + tx;
        hi[o] = h;
        lo[o] = __float2bfloat16(x - __bfloat162float(h));
    }
}

// ---------------- split-bf16 tensor-core GEMM ----------------------------------
// C[4096, N] = A[4096, K] @ B[K, N] in fp32 accuracy via 3 bf16 passes:
// Ahi@Bhi + Alo@Bhi + Ahi@Blo. B supplied transposed/split as [N][K] bf16.
// Block tile 128x128, 8 warps (2x4), warp tile 64x32, mma m16n8k16.
// perm=1: output row r=(t*64+b) stored at row (b*T+t).
__global__ __launch_bounds__(256) void mma_gemm_k(
    const __nv_bfloat16* __restrict__ Ahi, const __nv_bfloat16* __restrict__ Alo,
    const __nv_bfloat16* __restrict__ Bhi, const __nv_bfloat16* __restrict__ Blo,
    const float* __restrict__ bias,
    float* __restrict__ out, int K, int N, int perm)
{
    __shared__ __nv_bfloat16 As[2][128][40];
    __shared__ __nv_bfloat16 Bs[2][128][40];

    const int tid  = threadIdx.x;
    const int row0 = blockIdx.x * 128;
    const int col0 = blockIdx.y * 128;
    const int wid  = tid >> 5, lane = tid & 31;
    const int wm   = wid >> 2;          // 0..1  (64 rows)
    const int wn   = wid & 3;           // 0..3  (32 cols)
    const int g    = lane >> 2, tg = lane & 3;

    const int kps  = K >> 5;            // k-tiles per segment
    const int nit  = 3 * kps;

    float acc[4][4][4];
#pragma unroll
    for (int im = 0; im < 4; im++)
#pragma unroll
        for (int in_ = 0; in_ < 4; in_++)
#pragma unroll
            for (int q = 0; q < 4; q++) acc[im][in_][q] = 0.f;

    // cp.async coords: A and B each 128 rows x 4 chunks(8 bf16) = 512 chunks
    const int ca  = tid * 2;
    const int ar0 = ca >> 2,       ao0 = (ca & 3) * 8;
    const int ar1 = (ca + 1) >> 2, ao1 = ((ca + 1) & 3) * 8;

    auto issue = [&](int it, int buf) {
        int s  = (it >= 2 * kps) ? 2 : (it >= kps ? 1 : 0);
        int k0 = (it - s * kps) * 32;
        const __nv_bfloat16* A = (s == 1) ? Alo : Ahi;
        const __nv_bfloat16* B = (s == 2) ? Blo : Bhi;
        cp16(&As[buf][ar0][ao0], A + (size_t)(row0 + ar0) * K + k0 + ao0);
        cp16(&As[buf][ar1][ao1], A + (size_t)(row0 + ar1) * K + k0 + ao1);
        cp16(&Bs[buf][ar0][ao0], B + (size_t)(col0 + ar0) * K + k0 + ao0);
        cp16(&Bs[buf][ar1][ao1], B + (size_t)(col0 + ar1) * K + k0 + ao1);
        cp_commit();
    };

    issue(0, 0);

#pragma unroll 1
    for (int it = 0; it < nit; it++) {
        const int buf = it & 1;
        if (it + 1 < nit) { issue(it + 1, buf ^ 1); cp_wait1(); }
        else              { cp_wait0(); }
        __syncthreads();

#pragma unroll
        for (int kk = 0; kk < 32; kk += 16) {
            unsigned a[4][4], b[4][2];
#pragma unroll
            for (int im = 0; im < 4; im++) {
                int r = wm * 64 + im * 16;
                a[im][0] = *(const unsigned*)&As[buf][r + g][kk + tg * 2];
                a[im][1] = *(const unsigned*)&As[buf][r + g + 8][kk + tg * 2];
                a[im][2] = *(const unsigned*)&As[buf][r + g][kk + tg * 2 + 8];
                a[im][3] = *(const unsigned*)&As[buf][r + g + 8][kk + tg * 2 + 8];
            }
#pragma unroll
            for (int in_ = 0; in_ < 4; in_++) {
                int nn = wn * 32 + in_ * 8 + g;
                b[in_][0] = *(const unsigned*)&Bs[buf][nn][kk + tg * 2];
                b[in_][1] = *(const unsigned*)&Bs[buf][nn][kk + tg * 2 + 8];
            }
#pragma unroll
            for (int im = 0; im < 4; im++)
#pragma unroll
                for (int in_ = 0; in_ < 4; in_++)
                    mma16816(acc[im][in_],
                             a[im][0], a[im][1], a[im][2], a[im][3],
                             b[in_][0], b[in_][1]);
        }
        __syncthreads();
    }

    // epilogue
#pragma unroll
    for (int im = 0; im < 4; im++) {
#pragma unroll
        for (int in_ = 0; in_ < 4; in_++) {
            int rr = row0 + wm * 64 + im * 16 + g;
            int cn = col0 + wn * 32 + in_ * 8 + tg * 2;
            float b0v = bias ? bias[cn] : 0.f;
            float b1v = bias ? bias[cn + 1] : 0.f;
#pragma unroll
            for (int half = 0; half < 2; half++) {
                int r = rr + half * 8;
                size_t orow;
                if (perm) {
                    int t = r >> 6, b = r & 63;
                    orow = (size_t)(b * Tt + t);
                } else {
                    orow = (size_t)r;
                }
                float2 v;
                v.x = acc[im][in_][half * 2 + 0] + b0v;
                v.y = acc[im][in_][half * 2 + 1] + b1v;
                *(float2*)(out + orow * N + cn) = v;
            }
        }
    }
}

// ---------------- wavefront LSTM cell (unchanged from round 3) ------------------
__global__ __launch_bounds__(128) void lstm_wave_k(CellArgs args, int s) {
    __shared__ float As[2][64][20];
    __shared__ float Bs[2][16][32];
    __shared__ float Zs[64][33];

    const int lmin = (s > 63) ? (s - 63) : 0;
    const int l    = lmin + blockIdx.y;
    const int t    = s - l;
    const size_t SH = (size_t)Bb * Hh;

    const float* hprev = g_h + (size_t)(l * 2 + (t & 1)) * SH;
    float*       hnew  = g_h + (size_t)(l * 2 + ((t + 1) & 1)) * SH;
    float*       c     = g_c + (size_t)l * SH;
    const float* x     = (l == 0) ? hprev
                                  : g_h + (size_t)((l - 1) * 2 + ((t + 1) & 1)) * SH;
    const float* zpre  = (l == 0) ? (g_zpre + (size_t)t * Bb * 4 * Hh) : nullptr;
    float*       h4st  = (l == 3) ? (g_h4 + (size_t)t * SH) : nullptr;
    const float* W     = args.W[l];
    const float* U     = args.U[l];
    const float* bias  = args.b[l];
    const int    n1    = (l == 0) ? 0 : 64;
    const int    n     = n1 + 64;

    const int tid = threadIdx.x;
    const int tx  = tid & 15;
    const int ty  = tid >> 4;
    const int j0  = blockIdx.x * 8;

    const int ac0 = tid * 2;
    const int ar0 = ac0 >> 2,       ao0 = (ac0 & 3) << 2;
    const int ar1 = (ac0 + 1) >> 2, ao1 = ((ac0 + 1) & 3) << 2;
    const int bkk = tid >> 3,       bc4 = (tid & 7) * 4;
    const int bgo = (bc4 >> 3) * Hh + j0 + (bc4 & 7);

    float acc[8][2];
#pragma unroll
    for (int i = 0; i < 8; i++) { acc[i][0] = 0.f; acc[i][1] = 0.f; }

    auto issue = [&](int i, int buf) {
        const float* Ai; const float* Bi; int k0;
        if (i < n1) { Ai = x;     Bi = W; k0 = i * 16; }
        else        { Ai = hprev; Bi = U; k0 = (i - n1) * 16; }
        cp16(&As[buf][ar0][ao0], Ai + (size_t)ar0 * Hh + k0 + ao0);
        cp16(&As[buf][ar1][ao1], Ai + (size_t)ar1 * Hh + k0 + ao1);
        cp16(&Bs[buf][bkk][bc4], Bi + (size_t)(k0 + bkk) * (4 * Hh) + bgo);
        cp_commit();
    };

    issue(0, 0);

#pragma unroll 1
    for (int i = 0; i < n; i++) {
        if (i + 1 < n) { issue(i + 1, (i + 1) & 1); cp_wait1(); }
        else           { cp_wait0(); }
        __syncthreads();
        const int buf = i & 1;
#pragma unroll
        for (int kk = 0; kk < 16; kk++) {
            float2 b2 = *(const float2*)&Bs[buf][kk][2 * tx];
            float a[8];
#pragma unroll
            for (int r = 0; r < 8; r++) a[r] = As[buf][ty * 8 + r][kk];
#pragma unroll
            for (int r = 0; r < 8; r++) {
                acc[r][0] = fmaf(a[r], b2.x, acc[r][0]);
                acc[r][1] = fmaf(a[r], b2.y, acc[r][1]);
            }
        }
        __syncthreads();
    }

#pragma unroll
    for (int i = 0; i < 8; i++) {
        Zs[ty * 8 + i][2 * tx]     = acc[i][0];
        Zs[ty * 8 + i][2 * tx + 1] = acc[i][1];
    }
    __syncthreads();

#pragma unroll
    for (int q = 0; q < 4; q++) {
        int e  = tid + 128 * q;
        int r  = e >> 3;
        int jj = e & 7;
        int j  = j0 + jj;
        float zi = Zs[r][0  + jj] + bias[j];
        float zf = Zs[r][8  + jj] + bias[Hh + j];
        float zg = Zs[r][16 + jj] + bias[2 * Hh + j];
        float zo = Zs[r][24 + jj] + bias[3 * Hh + j];
        if (zpre) {
            const float* zp = zpre + (size_t)r * (4 * Hh);
            zi += zp[j];
            zf += zp[Hh + j];
            zg += zp[2 * Hh + j];
            zo += zp[3 * Hh + j];
        }
        float si = 1.f / (1.f + __expf(-zi));
        float sf = 1.f / (1.f + __expf(-zf));
        float so = 1.f / (1.f + __expf(-zo));
        float tg = tanhf(zg);
        float cn = sf * c[r * Hh + j] + si * tg;
        float hn = so * tanhf(cn);
        c[r * Hh + j]    = cn;
        hnew[r * Hh + j] = hn;
        if (h4st) h4st[r * Hh + j] = hn;
    }
}

// ---------------- in-place row softmax over V ----------------------------------
__global__ __launch_bounds__(256) void softmax_k(float* __restrict__ out) {
    __shared__ float red[256];
    float* p = out + (size_t)blockIdx.x * Vv;
    int tid = threadIdx.x;

    float m = -3.4e38f;
    for (int i = tid; i < Vv; i += 256) m = fmaxf(m, p[i]);
    red[tid] = m; __syncthreads();
    for (int s = 128; s > 0; s >>= 1) {
        if (tid < s) red[tid] = fmaxf(red[tid], red[tid + s]);
        __syncthreads();
    }
    m = red[0]; __syncthreads();

    float s = 0.f;
    for (int i = tid; i < Vv; i += 256) s += __expf(p[i] - m);
    red[tid] = s; __syncthreads();
    for (int st = 128; st > 0; st >>= 1) {
        if (tid < st) red[tid] += red[tid + st];
        __syncthreads();
    }
    float inv = 1.f / red[0];

    for (int i = tid; i < Vv; i += 256) p[i] = __expf(p[i] - m) * inv;
}

// ---------------- launch ------------------------------------------------------
extern "C" void kernel_launch(void* const* d_in, const int* in_sizes, int n_in,
                              void* d_out, int out_size) {
    (void)in_sizes; (void)n_in; (void)out_size;
    const int*   tok = (const int*)d_in[0];
    const float* emb = (const float*)d_in[9];
    CellArgs args;
    for (int l = 0; l < 4; l++) {
        args.W[l] = (const float*)d_in[10 + 3 * l];
        args.U[l] = (const float*)d_in[11 + 3 * l];
        args.b[l] = (const float*)d_in[12 + 3 * l];
    }
    const float* Wfc = (const float*)d_in[22];
    const float* bfc = (const float*)d_in[23];
    float* out = (float*)d_out;

    float *xbuf, *hbuf, *cbuf, *h4, *zpre;
    __nv_bfloat16 *Ahi, *Alo, *B1hi, *B1lo, *Bhi, *Blo;
    cudaGetSymbolAddress((void**)&xbuf, g_xbuf);
    cudaGetSymbolAddress((void**)&hbuf, g_h);
    cudaGetSymbolAddress((void**)&cbuf, g_c);
    cudaGetSymbolAddress((void**)&h4,   g_h4);
    cudaGetSymbolAddress((void**)&zpre, g_zpre);
    cudaGetSymbolAddress((void**)&Ahi,  g_Ahi);
    cudaGetSymbolAddress((void**)&Alo,  g_Alo);
    cudaGetSymbolAddress((void**)&B1hi, g_B1hi);
    cudaGetSymbolAddress((void**)&B1lo, g_B1lo);
    cudaGetSymbolAddress((void**)&Bhi,  g_Bhi);
    cudaGetSymbolAddress((void**)&Blo,  g_Blo);

    const size_t SH = (size_t)Bb * Hh;

    for (int l = 0; l < 4; l++) {
        cudaMemcpyAsync(hbuf + (size_t)(l * 2 + 0) * SH, d_in[1 + 2 * l],
                        SH * sizeof(float), cudaMemcpyDeviceToDevice, 0);
        cudaMemcpyAsync(cbuf + (size_t)l * SH, d_in[2 + 2 * l],
                        SH * sizeof(float), cudaMemcpyDeviceToDevice, 0);
    }

    embed_k<<<(Tt * Bb * Ee) / 256, 256>>>(tok, emb);

    // zpre = x @ W1 on tensor cores (split-bf16)
    split_k<<<(4096 * 512) / 256, 256>>>(xbuf, Ahi, Alo, 4096 * 512);
    tsplit_k<<<dim3(Ee / 32, (4 * Hh) / 32), 256>>>(args.W[0], B1hi, B1lo, Ee, 4 * Hh);
    mma_gemm_k<<<dim3(32, (4 * Hh) / 128), 256>>>(
        Ahi, Alo, B1hi, B1lo, nullptr, zpre, Ee, 4 * Hh, 0);

    // wavefront over diagonals s = t + l
    for (int s = 0; s <= Tt + 3 - 1; s++) {
        int lmin = (s > Tt - 1) ? (s - (Tt - 1)) : 0;
        int lmax = (s < 3) ? s : 3;
        int ny   = lmax - lmin + 1;
        lstm_wave_k<<<dim3(Hh / 8, ny), 128>>>(args, s);
    }

    // FC on tensor cores (split-bf16)
    tsplit_k<<<dim3(Hh / 32, Vv / 32), 256>>>(Wfc, Bhi, Blo, Hh, Vv);
    split_k<<<(4096 * 1024) / 256, 256>>>(h4, Ahi, Alo, 4096 * 1024);
    mma_gemm_k<<<dim3(32, Vv / 128), 256>>>(
        Ahi, Alo, Bhi, Blo, bfc, out, Hh, Vv, 1);

    softmax_k<<<Bb * Tt, 256>>>(out);
}

// round 5
// speedup vs baseline: 4.7894x; 1.3113x over previous
#include <cuda_runtime.h>
#include <cuda_bf16.h>

#define Bb 64
#define Tt 64
#define Hh 1024
#define Vv 32000
#define Ee 512
#define WHH (4 * Hh * Hh)

// ---------------- scratch (static device memory; no allocation) ----------------
__device__ float g_xbuf[Tt * Bb * Ee];          // embedded inputs
__device__ float g_h[8 * Bb * Hh];              // fp32 initial h staging (4 slots used)
__device__ float g_c[4 * Bb * Hh];              // 4 layers c (fp32, in-place)
__device__ float g_zpre[Tt * Bb * 4 * Hh];      // precomputed x@W1
__device__ __nv_bfloat16 g_Ahi[4096 * 1024];    // GEMM A splits (x for zpre, h4 for FC)
__device__ __nv_bfloat16 g_Alo[4096 * 1024];
__device__ __nv_bfloat16 g_B1hi[4096 * 512];    // W1^T split  [4H][E]
__device__ __nv_bfloat16 g_B1lo[4096 * 512];
__device__ __nv_bfloat16 g_Bhi[(size_t)Vv * 1024];  // Wfc^T split [V][H]
__device__ __nv_bfloat16 g_Blo[(size_t)Vv * 1024];
__device__ __nv_bfloat16 g_hsp_hi[8 * Bb * Hh]; // h state splits, 4 layers x ping-pong
__device__ __nv_bfloat16 g_hsp_lo[8 * Bb * Hh];
__device__ __nv_bfloat16 g_Wsp_hi[3 * WHH];     // W2..W4 ^T split [4H][H]
__device__ __nv_bfloat16 g_Wsp_lo[3 * WHH];
__device__ __nv_bfloat16 g_Usp_hi[4 * WHH];     // U1..U4 ^T split [4H][H]
__device__ __nv_bfloat16 g_Usp_lo[4 * WHH];

struct CellArgs {
    const float* b[4];
};

// ---------------- cp.async helpers ---------------------------------------------
__device__ __forceinline__ void cp16(void* smem_dst, const void* gsrc) {
    unsigned s = (unsigned)__cvta_generic_to_shared(smem_dst);
    asm volatile("cp.async.cg.shared.global [%0], [%1], 16;\n" :: "r"(s), "l"(gsrc));
}
__device__ __forceinline__ void cp_commit() {
    asm volatile("cp.async.commit_group;\n" ::: "memory");
}
__device__ __forceinline__ void cp_wait2() {
    asm volatile("cp.async.wait_group 2;\n" ::: "memory");
}
__device__ __forceinline__ void cp_wait1() {
    asm volatile("cp.async.wait_group 1;\n" ::: "memory");
}
__device__ __forceinline__ void cp_wait0() {
    asm volatile("cp.async.wait_group 0;\n" ::: "memory");
}

// ---------------- bf16 mma helper ----------------------------------------------
__device__ __forceinline__ void mma16816(float c[4],
                                         unsigned a0, unsigned a1, unsigned a2, unsigned a3,
                                         unsigned b0, unsigned b1) {
    asm volatile(
        "mma.sync.aligned.m16n8k16.row.col.f32.bf16.bf16.f32 "
        "{%0,%1,%2,%3}, {%4,%5,%6,%7}, {%8,%9}, {%0,%1,%2,%3};"
        : "+f"(c[0]), "+f"(c[1]), "+f"(c[2]), "+f"(c[3])
        : "r"(a0), "r"(a1), "r"(a2), "r"(a3), "r"(b0), "r"(b1));
}

// ---------------- embedding lookup ---------------------------------------------
__global__ __launch_bounds__(256) void embed_k(const int* __restrict__ tok,
                                               const float* __restrict__ emb) {
    int idx = blockIdx.x * 256 + threadIdx.x;
    int e  = idx & (Ee - 1);
    int bt = idx >> 9;
    int b  = bt & (Bb - 1);
    int t  = bt >> 6;
    g_xbuf[idx] = emb[(size_t)tok[b * Tt + t] * Ee + e];
}

// ---------------- fp32 -> (hi, lo) bf16 split ----------------------------------
__global__ __launch_bounds__(256) void split_k(const float* __restrict__ src,
                                               __nv_bfloat16* __restrict__ hi,
                                               __nv_bfloat16* __restrict__ lo, int n) {
    int i = blockIdx.x * 256 + threadIdx.x;
    if (i < n) {
        float x = src[i];
        __nv_bfloat16 h = __float2bfloat16(x);
        hi[i] = h;
        lo[i] = __float2bfloat16(x - __bfloat162float(h));
    }
}

// ---------------- split initial h states into hsp slots (l*2 + 0) ---------------
__global__ __launch_bounds__(256) void hinit_split_k() {
    int i = blockIdx.x * 256 + threadIdx.x;       // over 4 * 65536
    int l = i >> 16;
    int r = i & 65535;
    size_t o = ((size_t)(l * 2)) * (Bb * Hh) + r;
    float x = g_h[o];
    __nv_bfloat16 h = __float2bfloat16(x);
    g_hsp_hi[o] = h;
    g_hsp_lo[o] = __float2bfloat16(x - __bfloat162float(h));
}

// ---------------- transpose + split: src[K][N] -> hi/lo [N][K] ------------------
__global__ __launch_bounds__(256) void tsplit_k(const float* __restrict__ src,
                                                __nv_bfloat16* __restrict__ hi,
                                                __nv_bfloat16* __restrict__ lo,
                                                int K, int N) {
    __shared__ float tile[32][33];
    int k0 = blockIdx.x * 32, n0 = blockIdx.y * 32;
    int tx = threadIdx.x & 31, ty = threadIdx.x >> 5;    // 32 x 8
#pragma unroll
    for (int j = 0; j < 32; j += 8)
        tile[ty + j][tx] = src[(size_t)(k0 + ty + j) * N + n0 + tx];
    __syncthreads();
#pragma unroll
    for (int j = 0; j < 32; j += 8) {
        float x = tile[tx][ty + j];
        __nv_bfloat16 h = __float2bfloat16(x);
        size_t o = (size_t)(n0 + ty + j) * K + k0 + tx;
        hi[o] = h;
        lo[o] = __float2bfloat16(x - __bfloat162float(h));
    }
}

// ---------------- split-bf16 tensor-core GEMM (zpre + FC) -----------------------
__global__ __launch_bounds__(256) void mma_gemm_k(
    const __nv_bfloat16* __restrict__ Ahi, const __nv_bfloat16* __restrict__ Alo,
    const __nv_bfloat16* __restrict__ Bhi, const __nv_bfloat16* __restrict__ Blo,
    const float* __restrict__ bias,
    float* __restrict__ out, int K, int N, int perm)
{
    __shared__ __nv_bfloat16 As[2][128][40];
    __shared__ __nv_bfloat16 Bs[2][128][40];

    const int tid  = threadIdx.x;
    const int row0 = blockIdx.x * 128;
    const int col0 = blockIdx.y * 128;
    const int wid  = tid >> 5, lane = tid & 31;
    const int wm   = wid >> 2;
    const int wn   = wid & 3;
    const int g    = lane >> 2, tg = lane & 3;

    const int kps  = K >> 5;
    const int nit  = 3 * kps;

    float acc[4][4][4];
#pragma unroll
    for (int im = 0; im < 4; im++)
#pragma unroll
        for (int in_ = 0; in_ < 4; in_++)
#pragma unroll
            for (int q = 0; q < 4; q++) acc[im][in_][q] = 0.f;

    const int ca  = tid * 2;
    const int ar0 = ca >> 2,       ao0 = (ca & 3) * 8;
    const int ar1 = (ca + 1) >> 2, ao1 = ((ca + 1) & 3) * 8;

    auto issue = [&](int it, int buf) {
        int s  = (it >= 2 * kps) ? 2 : (it >= kps ? 1 : 0);
        int k0 = (it - s * kps) * 32;
        const __nv_bfloat16* A = (s == 1) ? Alo : Ahi;
        const __nv_bfloat16* B = (s == 2) ? Blo : Bhi;
        cp16(&As[buf][ar0][ao0], A + (size_t)(row0 + ar0) * K + k0 + ao0);
        cp16(&As[buf][ar1][ao1], A + (size_t)(row0 + ar1) * K + k0 + ao1);
        cp16(&Bs[buf][ar0][ao0], B + (size_t)(col0 + ar0) * K + k0 + ao0);
        cp16(&Bs[buf][ar1][ao1], B + (size_t)(col0 + ar1) * K + k0 + ao1);
        cp_commit();
    };

    issue(0, 0);

#pragma unroll 1
    for (int it = 0; it < nit; it++) {
        const int buf = it & 1;
        if (it + 1 < nit) { issue(it + 1, buf ^ 1); cp_wait1(); }
        else              { cp_wait0(); }
        __syncthreads();

#pragma unroll
        for (int kk = 0; kk < 32; kk += 16) {
            unsigned a[4][4], b[4][2];
#pragma unroll
            for (int im = 0; im < 4; im++) {
                int r = wm * 64 + im * 16;
                a[im][0] = *(const unsigned*)&As[buf][r + g][kk + tg * 2];
                a[im][1] = *(const unsigned*)&As[buf][r + g + 8][kk + tg * 2];
                a[im][2] = *(const unsigned*)&As[buf][r + g][kk + tg * 2 + 8];
                a[im][3] = *(const unsigned*)&As[buf][r + g + 8][kk + tg * 2 + 8];
            }
#pragma unroll
            for (int in_ = 0; in_ < 4; in_++) {
                int nn = wn * 32 + in_ * 8 + g;
                b[in_][0] = *(const unsigned*)&Bs[buf][nn][kk + tg * 2];
                b[in_][1] = *(const unsigned*)&Bs[buf][nn][kk + tg * 2 + 8];
            }
#pragma unroll
            for (int im = 0; im < 4; im++)
#pragma unroll
                for (int in_ = 0; in_ < 4; in_++)
                    mma16816(acc[im][in_],
                             a[im][0], a[im][1], a[im][2], a[im][3],
                             b[in_][0], b[in_][1]);
        }
        __syncthreads();
    }

#pragma unroll
    for (int im = 0; im < 4; im++) {
#pragma unroll
        for (int in_ = 0; in_ < 4; in_++) {
            int rr = row0 + wm * 64 + im * 16 + g;
            int cn = col0 + wn * 32 + in_ * 8 + tg * 2;
            float b0v = bias ? bias[cn] : 0.f;
            float b1v = bias ? bias[cn + 1] : 0.f;
#pragma unroll
            for (int half = 0; half < 2; half++) {
                int r = rr + half * 8;
                size_t orow;
                if (perm) {
                    int t = r >> 6, b = r & 63;
                    orow = (size_t)(b * Tt + t);
                } else {
                    orow = (size_t)r;
                }
                float2 v;
                v.x = acc[im][in_][half * 2 + 0] + b0v;
                v.y = acc[im][in_][half * 2 + 1] + b1v;
                *(float2*)(out + orow * N + cn) = v;
            }
        }
    }
}

// ---------------- wavefront LSTM cell on tensor cores ---------------------------
// Diagonal s = t + l. Block: 16 hidden units x 4 gates (local C [64 x 64]),
// 128 threads = 4 warps, warp tile 64x16 (4 m16 x 2 n8). Split-bf16 3-pass GEMM.
__global__ __launch_bounds__(128) void lstm_wave_mma_k(CellArgs args, int s) {
    __shared__ __nv_bfloat16 As[3][64][40];
    __shared__ __nv_bfloat16 Bs[3][64][40];
    __shared__ float Zs[64][68];

    const int lmin = (s > 63) ? (s - 63) : 0;
    const int l    = lmin + blockIdx.y;
    const int t    = s - l;
    const size_t SH = (size_t)Bb * Hh;
    const int pin  = t & 1, pout = (t + 1) & 1;
    const int j0   = blockIdx.x * 16;

    const __nv_bfloat16* h_hi = g_hsp_hi + (size_t)(l * 2 + pin) * SH;
    const __nv_bfloat16* h_lo = g_hsp_lo + (size_t)(l * 2 + pin) * SH;
    const __nv_bfloat16* Uhi  = g_Usp_hi + (size_t)l * WHH;
    const __nv_bfloat16* Ulo  = g_Usp_lo + (size_t)l * WHH;

    const __nv_bfloat16* Aseg[6];
    const __nv_bfloat16* Bseg[6];
    int nseg;
    if (l == 0) {
        Aseg[0] = h_hi; Bseg[0] = Uhi;
        Aseg[1] = h_lo; Bseg[1] = Uhi;
        Aseg[2] = h_hi; Bseg[2] = Ulo;
        nseg = 3;
    } else {
        const __nv_bfloat16* x_hi = g_hsp_hi + (size_t)((l - 1) * 2 + pout) * SH;
        const __nv_bfloat16* x_lo = g_hsp_lo + (size_t)((l - 1) * 2 + pout) * SH;
        const __nv_bfloat16* Whi  = g_Wsp_hi + (size_t)(l - 1) * WHH;
        const __nv_bfloat16* Wlo  = g_Wsp_lo + (size_t)(l - 1) * WHH;
        Aseg[0] = x_hi; Bseg[0] = Whi;
        Aseg[1] = x_lo; Bseg[1] = Whi;
        Aseg[2] = x_hi; Bseg[2] = Wlo;
        Aseg[3] = h_hi; Bseg[3] = Uhi;
        Aseg[4] = h_lo; Bseg[4] = Uhi;
        Aseg[5] = h_hi; Bseg[5] = Ulo;
        nseg = 6;
    }
    const int nit = nseg * 32;      // K = 1024 per segment, 32-wide chunks

    const int tid  = threadIdx.x;
    const int wn   = tid >> 5;      // warp -> local n range [wn*16, wn*16+16)
    const int lane = tid & 31;
    const int g    = lane >> 2, tg = lane & 3;

    // cp.async coords: A/B tiles 64 rows x 32 k; per thread one row, 2x16B
    const int arow = tid >> 1;
    const int aoff = (tid & 1) * 16;
    const int bglob = ((arow >> 4) << 10) + j0 + (arow & 15);   // gate*1024 + unit

    float acc[4][2][4];
#pragma unroll
    for (int im = 0; im < 4; im++)
#pragma unroll
        for (int in_ = 0; in_ < 2; in_++)
#pragma unroll
            for (int q = 0; q < 4; q++) acc[im][in_][q] = 0.f;

    auto issue = [&](int it, int buf) {
        int seg = it >> 5;
        int k0  = (it & 31) * 32;
        const __nv_bfloat16* A  = Aseg[seg];
        const __nv_bfloat16* Bp = Bseg[seg];
        cp16(&As[buf][arow][aoff],     A + (size_t)arow * Hh + k0 + aoff);
        cp16(&As[buf][arow][aoff + 8], A + (size_t)arow * Hh + k0 + aoff + 8);
        cp16(&Bs[buf][arow][aoff],     Bp + (size_t)bglob * Hh + k0 + aoff);
        cp16(&Bs[buf][arow][aoff + 8], Bp + (size_t)bglob * Hh + k0 + aoff + 8);
        cp_commit();
    };

    issue(0, 0);
    issue(1, 1);

#pragma unroll 1
    for (int it = 0; it < nit; it++) {
        if (it + 2 < nit) { issue(it + 2, (it + 2) % 3); cp_wait2(); }
        else if (it + 1 < nit) { cp_wait1(); }
        else { cp_wait0(); }
        __syncthreads();
        const int buf = it % 3;

#pragma unroll
        for (int kk = 0; kk < 32; kk += 16) {
            unsigned a[4][4], b[2][2];
#pragma unroll
            for (int im = 0; im < 4; im++) {
                int r = im * 16;
                a[im][0] = *(const unsigned*)&As[buf][r + g][kk + tg * 2];
                a[im][1] = *(const unsigned*)&As[buf][r + g + 8][kk + tg * 2];
                a[im][2] = *(const unsigned*)&As[buf][r + g][kk + tg * 2 + 8];
                a[im][3] = *(const unsigned*)&As[buf][r + g + 8][kk + tg * 2 + 8];
            }
#pragma unroll
            for (int in_ = 0; in_ < 2; in_++) {
                int nn = wn * 16 + in_ * 8 + g;
                b[in_][0] = *(const unsigned*)&Bs[buf][nn][kk + tg * 2];
                b[in_][1] = *(const unsigned*)&Bs[buf][nn][kk + tg * 2 + 8];
            }
#pragma unroll
            for (int im = 0; im < 4; im++)
#pragma unroll
                for (int in_ = 0; in_ < 2; in_++)
                    mma16816(acc[im][in_],
                             a[im][0], a[im][1], a[im][2], a[im][3],
                             b[in_][0], b[in_][1]);
        }
        __syncthreads();
    }

    // scatter z fragments to smem for gate assembly
#pragma unroll
    for (int im = 0; im < 4; im++)
#pragma unroll
        for (int in_ = 0; in_ < 2; in_++)
#pragma unroll
            for (int q = 0; q < 4; q++) {
                int r = im * 16 + g + ((q >> 1) << 3);
                int n = wn * 16 + in_ * 8 + tg * 2 + (q & 1);
                Zs[r][n] = acc[im][in_][q];
            }
    __syncthreads();

    // gate epilogue: 64 rows x 16 units, 8 per thread
    const float* bias = args.b[l];
    float* c = g_c + (size_t)l * SH;
    __nv_bfloat16* ho_hi = g_hsp_hi + (size_t)(l * 2 + pout) * SH;
    __nv_bfloat16* ho_lo = g_hsp_lo + (size_t)(l * 2 + pout) * SH;
    const float* zp = (l == 0) ? (g_zpre + (size_t)t * Bb * 4 * Hh) : nullptr;

#pragma unroll
    for (int q = 0; q < 8; q++) {
        int e  = tid + 128 * q;       // 0..1023
        int r  = e >> 4;
        int uu = e & 15;
        int j  = j0 + uu;
        float zi = Zs[r][uu]      + bias[j];
        float zf = Zs[r][16 + uu] + bias[Hh + j];
        float zg = Zs[r][32 + uu] + bias[2 * Hh + j];
        float zo = Zs[r][48 + uu] + bias[3 * Hh + j];
        if (zp) {
            const float* z = zp + (size_t)r * (4 * Hh);
            zi += z[j]; zf += z[Hh + j]; zg += z[2 * Hh + j]; zo += z[3 * Hh + j];
        }
        float si = 1.f / (1.f + __expf(-zi));
        float sf = 1.f / (1.f + __expf(-zf));
        float so = 1.f / (1.f + __expf(-zo));
        float tg_ = tanhf(zg);
        float cn = sf * c[r * Hh + j] + si * tg_;
        float hn = so * tanhf(cn);
        c[r * Hh + j] = cn;
        __nv_bfloat16 hh = __float2bfloat16(hn);
        ho_hi[r * Hh + j] = hh;
        ho_lo[r * Hh + j] = __float2bfloat16(hn - __bfloat162float(hh));
        if (l == 3) {
            size_t o = ((size_t)t * Bb + r) * Hh + j;
            g_Ahi[o] = hh;
            g_Alo[o] = __float2bfloat16(hn - __bfloat162float(hh));
        }
    }
}

// ---------------- in-place row softmax over V ----------------------------------
__global__ __launch_bounds__(256) void softmax_k(float* __restrict__ out) {
    __shared__ float red[256];
    float* p = out + (size_t)blockIdx.x * Vv;
    int tid = threadIdx.x;

    float m = -3.4e38f;
    for (int i = tid; i < Vv; i += 256) m = fmaxf(m, p[i]);
    red[tid] = m; __syncthreads();
    for (int s = 128; s > 0; s >>= 1) {
        if (tid < s) red[tid] = fmaxf(red[tid], red[tid + s]);
        __syncthreads();
    }
    m = red[0]; __syncthreads();

    float s = 0.f;
    for (int i = tid; i < Vv; i += 256) s += __expf(p[i] - m);
    red[tid] = s; __syncthreads();
    for (int st = 128; st > 0; st >>= 1) {
        if (tid < st) red[tid] += red[tid + st];
        __syncthreads();
    }
    float inv = 1.f / red[0];

    for (int i = tid; i < Vv; i += 256) p[i] = __expf(p[i] - m) * inv;
}

// ---------------- launch ------------------------------------------------------
extern "C" void kernel_launch(void* const* d_in, const int* in_sizes, int n_in,
                              void* d_out, int out_size) {
    (void)in_sizes; (void)n_in; (void)out_size;
    const int*   tok = (const int*)d_in[0];
    const float* emb = (const float*)d_in[9];
    const float* W[4]; const float* U[4];
    CellArgs args;
    for (int l = 0; l < 4; l++) {
        W[l] = (const float*)d_in[10 + 3 * l];
        U[l] = (const float*)d_in[11 + 3 * l];
        args.b[l] = (const float*)d_in[12 + 3 * l];
    }
    const float* Wfc = (const float*)d_in[22];
    const float* bfc = (const float*)d_in[23];
    float* out = (float*)d_out;

    float *xbuf, *hbuf, *cbuf, *zpre;
    __nv_bfloat16 *Ahi, *Alo, *B1hi, *B1lo, *Bhi, *Blo, *Wsph, *Wspl, *Usph, *Uspl;
    cudaGetSymbolAddress((void**)&xbuf, g_xbuf);
    cudaGetSymbolAddress((void**)&hbuf, g_h);
    cudaGetSymbolAddress((void**)&cbuf, g_c);
    cudaGetSymbolAddress((void**)&zpre, g_zpre);
    cudaGetSymbolAddress((void**)&Ahi,  g_Ahi);
    cudaGetSymbolAddress((void**)&Alo,  g_Alo);
    cudaGetSymbolAddress((void**)&B1hi, g_B1hi);
    cudaGetSymbolAddress((void**)&B1lo, g_B1lo);
    cudaGetSymbolAddress((void**)&Bhi,  g_Bhi);
    cudaGetSymbolAddress((void**)&Blo,  g_Blo);
    cudaGetSymbolAddress((void**)&Wsph, g_Wsp_hi);
    cudaGetSymbolAddress((void**)&Wspl, g_Wsp_lo);
    cudaGetSymbolAddress((void**)&Usph, g_Usp_hi);
    cudaGetSymbolAddress((void**)&Uspl, g_Usp_lo);

    const size_t SH = (size_t)Bb * Hh;

    for (int l = 0; l < 4; l++) {
        cudaMemcpyAsync(hbuf + (size_t)(l * 2) * SH, d_in[1 + 2 * l],
                        SH * sizeof(float), cudaMemcpyDeviceToDevice, 0);
        cudaMemcpyAsync(cbuf + (size_t)l * SH, d_in[2 + 2 * l],
                        SH * sizeof(float), cudaMemcpyDeviceToDevice, 0);
    }

    embed_k<<<(Tt * Bb * Ee) / 256, 256>>>(tok, emb);
    hinit_split_k<<<(4 * Bb * Hh) / 256, 256>>>();

    // zpre = x @ W1 on tensor cores
    split_k<<<(4096 * 512) / 256, 256>>>(xbuf, Ahi, Alo, 4096 * 512);
    tsplit_k<<<dim3(Ee / 32, (4 * Hh) / 32), 256>>>(W[0], B1hi, B1lo, Ee, 4 * Hh);
    mma_gemm_k<<<dim3(32, (4 * Hh) / 128), 256>>>(
        Ahi, Alo, B1hi, B1lo, nullptr, zpre, Ee, 4 * Hh, 0);

    // transpose+split recurrent weights: W2..W4, U1..U4 -> [4H][H]
    for (int l = 1; l < 4; l++)
        tsplit_k<<<dim3(Hh / 32, (4 * Hh) / 32), 256>>>(
            W[l], Wsph + (size_t)(l - 1) * WHH, Wspl + (size_t)(l - 1) * WHH,
            Hh, 4 * Hh);
    for (int l = 0; l < 4; l++)
        tsplit_k<<<dim3(Hh / 32, (4 * Hh) / 32), 256>>>(
            U[l], Usph + (size_t)l * WHH, Uspl + (size_t)l * WHH, Hh, 4 * Hh);

    // wavefront over diagonals s = t + l (tensor-core cells)
    for (int s = 0; s <= Tt + 3 - 1; s++) {
        int lmin = (s > Tt - 1) ? (s - (Tt - 1)) : 0;
        int lmax = (s < 3) ? s : 3;
        int ny   = lmax - lmin + 1;
        lstm_wave_mma_k<<<dim3(Hh / 16, ny), 128>>>(args, s);
    }

    // FC on tensor cores (A splits written by the wave epilogue at l==3)
    tsplit_k<<<dim3(Hh / 32, Vv / 32), 256>>>(Wfc, Bhi, Blo, Hh, Vv);
    mma_gemm_k<<<dim3(32, Vv / 128), 256>>>(
        Ahi, Alo, Bhi, Blo, bfc, out, Hh, Vv, 1);

    softmax_k<<<Bb * Tt, 256>>>(out);
}